// round 5
// baseline (speedup 1.0000x reference)
#include <cuda_runtime.h>
#include <cstdint>
#include <cstddef>

#define ND     8192
#define DSK    1024
#define MCOLS  4096
#define KC     32
#define NCHUNK (ND / KC)          /* 256 */

// A' scratch: A'[d][k] = D[k]*w(k)*cos(pi*(2*P[d]+1)*k/(2N)), tf32-rounded bits
__device__ float g_A[(size_t)DSK * ND];

// ---------------------------------------------------------------------------
static __device__ __forceinline__ uint32_t smem_u32(const void* p) {
    uint32_t a;
    asm("{ .reg .u64 t; cvta.to.shared.u64 t, %1; cvt.u32.u64 %0, t; }" : "=r"(a) : "l"(p));
    return a;
}

#define CP_ASYNC16(dst, src) \
    asm volatile("cp.async.cg.shared.global [%0], [%1], 16;" :: "r"(dst), "l"(src))
#define CP_COMMIT()  asm volatile("cp.async.commit_group;" ::: "memory")
#define CP_WAIT0()   asm volatile("cp.async.wait_group 0;" ::: "memory")

static __device__ __forceinline__ uint32_t lds_u32(uint32_t addr) {
    uint32_t v;
    asm volatile("ld.shared.b32 %0, [%1];" : "=r"(v) : "r"(addr));
    return v;
}
static __device__ __forceinline__ float lds_f32(uint32_t addr) {
    float v;
    asm volatile("ld.shared.f32 %0, [%1];" : "=f"(v) : "r"(addr));
    return v;
}
// tf32 destination must be a .b32 register ("=r"), NOT .f32
static __device__ __forceinline__ uint32_t f2tf32(float f) {
    uint32_t u;
    asm("cvt.rna.tf32.f32 %0, %1;" : "=r"(u) : "f"(f));
    return u;
}
static __device__ __forceinline__ void mma_tf32(float* c, uint32_t a0, uint32_t a1,
                                                uint32_t a2, uint32_t a3,
                                                uint32_t b0, uint32_t b1) {
    asm volatile(
        "mma.sync.aligned.m16n8k8.row.col.f32.tf32.tf32.f32 "
        "{%0,%1,%2,%3}, {%4,%5,%6,%7}, {%8,%9}, {%0,%1,%2,%3};"
        : "+f"(c[0]), "+f"(c[1]), "+f"(c[2]), "+f"(c[3])
        : "r"(a0), "r"(a1), "r"(a2), "r"(a3), "r"(b0), "r"(b1));
}

// ---------------------------------------------------------------------------
// Kernel 1: precompute A' (tf32-rounded). Exact integer angle reduction:
// j = ((2n+1)*k) mod 4N ; ang = pi * j / (2N*2)
// ---------------------------------------------------------------------------
__global__ void __launch_bounds__(256) precompute_A(const float* __restrict__ D,
                                                    const int* __restrict__ P) {
    int idx = blockIdx.x * 256 + threadIdx.x;
    int d = idx >> 13;            // / 8192
    int k = idx & (ND - 1);
    int n = P[d];
    unsigned j = ((unsigned)(2 * n + 1) * (unsigned)k) & (4u * ND - 1u);   // mod 32768
    float ang = (float)j * 1.9174759848570515e-4f;                         // pi/16384
    float c = cosf(ang);
    float w = (k == 0) ? (0.5f / (float)ND) : (1.0f / (float)ND);
    float v = D[k] * w * c;
    g_A[idx] = __uint_as_float(f2tf32(v));    // store tf32-rounded bits
}

// ---------------------------------------------------------------------------
// Kernel 2: out[1024,4096] = A'[1024,8192] @ M[8192,4096] with mma.sync tf32.
// CTA tile 128(d) x 128(m), KC=32, double-buffered cp.async, 8 warps (2x4).
// SMEM layouts (padded rows, no transposes):
//   As[m 0..127][k 0..31]  row stride 144 B   (A' gmem rows are k-contiguous)
//   Bs[k 0..31][m 0..127]  row stride 528 B   (M  gmem rows are m-contiguous)
// ---------------------------------------------------------------------------
#define A_STRIDE 144u
#define B_STRIDE 528u
#define A_BYTES  (128u * A_STRIDE)               /* 18432 */
#define B_BYTES  (32u * B_STRIDE)                /* 16896 */
#define BUF_BYTES (A_BYTES + B_BYTES)            /* 35328 */
#define SMEM_REQ (2u * BUF_BYTES + 16u)

__global__ void __launch_bounds__(256, 2) srft_gemm(const float* __restrict__ Mmat,
                                                    float* __restrict__ out) {
    extern __shared__ char smem[];
    const uint32_t sb = smem_u32(smem);

    const int tid = threadIdx.x;
    const int wid = tid >> 5;
    const int lid = tid & 31;
    const int dt0 = blockIdx.x * 128;        // d-tile (8)
    const int nt0 = blockIdx.y * 128;        // m-tile (32)
    const int mw  = (wid >> 2) * 64;         // warp 64 rows
    const int nw  = (wid & 3) * 32;          // warp 32 cols

    const float* Aptr = g_A + (size_t)dt0 * ND;
    const float* Bptr = Mmat + nt0;

    float acc[4][4][4];
    #pragma unroll
    for (int i = 0; i < 4; i++)
        #pragma unroll
        for (int j = 0; j < 4; j++)
            #pragma unroll
            for (int q = 0; q < 4; q++) acc[i][j][q] = 0.f;

    // A fill: 4 quads: idx = tid + i*256 -> r = idx>>3 (row m), q = idx&7 (16B quad)
    // B fill: 4 quads: idx = tid + i*256 -> k = idx>>5,          q = idx&31
    auto fill = [&](uint32_t buf, int k0) {
        const uint32_t ab = sb + buf * BUF_BYTES;
        const uint32_t bb = ab + A_BYTES;
        #pragma unroll
        for (int i = 0; i < 4; i++) {
            int idx = tid + i * 256;
            int r = idx >> 3, q = idx & 7;
            CP_ASYNC16(ab + (uint32_t)r * A_STRIDE + (uint32_t)q * 16u,
                       Aptr + (size_t)r * ND + k0 + q * 4);
        }
        #pragma unroll
        for (int i = 0; i < 4; i++) {
            int idx = tid + i * 256;
            int k = idx >> 5, q = idx & 31;
            CP_ASYNC16(bb + (uint32_t)k * B_STRIDE + (uint32_t)q * 16u,
                       Bptr + (size_t)(k0 + k) * MCOLS + q * 4);
        }
        CP_COMMIT();
    };

    fill(0, 0);
    CP_WAIT0();
    __syncthreads();

    for (int c = 0; c < NCHUNK; c++) {
        const uint32_t buf = (uint32_t)(c & 1);
        if (c + 1 < NCHUNK) fill(buf ^ 1u, (c + 1) * KC);

        const uint32_t ab = sb + buf * BUF_BYTES;
        const uint32_t bb = ab + A_BYTES;
        const uint32_t a_base = ab + (uint32_t)(mw + (lid >> 2)) * A_STRIDE + (uint32_t)(lid & 3) * 4u;
        const uint32_t b_base = bb + (uint32_t)(lid & 3) * B_STRIDE + (uint32_t)(nw + (lid >> 2)) * 4u;

        #pragma unroll
        for (int kk = 0; kk < 4; kk++) {
            // B fragments: B[k][n], k = kk*8 + lane%4 (+4), n = nw + nf*8 + lane/4
            uint32_t bfr[4][2];
            #pragma unroll
            for (int nf = 0; nf < 4; nf++) {
                uint32_t a0 = b_base + (uint32_t)(kk * 8) * B_STRIDE + (uint32_t)(nf * 8) * 4u;
                bfr[nf][0] = f2tf32(lds_f32(a0));
                bfr[nf][1] = f2tf32(lds_f32(a0 + 4u * B_STRIDE));
            }
            #pragma unroll
            for (int ms = 0; ms < 4; ms++) {
                uint32_t aa = a_base + (uint32_t)(ms * 16) * A_STRIDE + (uint32_t)(kk * 8) * 4u;
                uint32_t a0 = lds_u32(aa);
                uint32_t a1 = lds_u32(aa + 8u * A_STRIDE);
                uint32_t a2 = lds_u32(aa + 16u);
                uint32_t a3 = lds_u32(aa + 8u * A_STRIDE + 16u);
                #pragma unroll
                for (int nf = 0; nf < 4; nf++)
                    mma_tf32(acc[ms][nf], a0, a1, a2, a3, bfr[nf][0], bfr[nf][1]);
            }
        }

        if (c + 1 < NCHUNK) CP_WAIT0();
        __syncthreads();
    }

    // Epilogue: direct STG (16 MB total, negligible)
    const int r_base = dt0 + mw + (lid >> 2);
    const int c_base = nt0 + nw + (lid & 3) * 2;
    #pragma unroll
    for (int ms = 0; ms < 4; ms++) {
        #pragma unroll
        for (int nf = 0; nf < 4; nf++) {
            int r0 = r_base + ms * 16;
            int cc = c_base + nf * 8;
            float2 v0 = make_float2(acc[ms][nf][0], acc[ms][nf][1]);
            float2 v1 = make_float2(acc[ms][nf][2], acc[ms][nf][3]);
            *reinterpret_cast<float2*>(out + (size_t)r0 * MCOLS + cc) = v0;
            *reinterpret_cast<float2*>(out + (size_t)(r0 + 8) * MCOLS + cc) = v1;
        }
    }
}

// ---------------------------------------------------------------------------
extern "C" void kernel_launch(void* const* d_in, const int* in_sizes, int n_in,
                              void* d_out, int out_size) {
    const float* Mmat = nullptr;
    const float* D = nullptr;
    const int*   P = nullptr;
    for (int i = 0; i < n_in; i++) {
        if (in_sizes[i] == ND * MCOLS)      Mmat = (const float*)d_in[i];
        else if (in_sizes[i] == ND)         D    = (const float*)d_in[i];
        else if (in_sizes[i] == DSK)        P    = (const int*)d_in[i];
    }

    precompute_A<<<(DSK * ND) / 256, 256>>>(D, P);

    cudaFuncSetAttribute(srft_gemm, cudaFuncAttributeMaxDynamicSharedMemorySize, SMEM_REQ);
    dim3 grid(8, 32);
    srft_gemm<<<grid, 256, SMEM_REQ>>>(Mmat, (float*)d_out);
}

// round 8
// speedup vs baseline: 1.1251x; 1.1251x over previous
#include <cuda_runtime.h>
#include <cstdint>
#include <cstddef>

#define ND     8192
#define DSK    1024
#define MCOLS  4096
#define KC     32
#define NCHUNK (ND / KC)          /* 256 */

// A' scratch: A'[d][k] = D[k]*w(k)*cos(pi*(2*P[d]+1)*k/(2N)), tf32-rounded bits
__device__ float g_A[(size_t)DSK * ND];

// ---------------------------------------------------------------------------
static __device__ __forceinline__ uint32_t smem_u32(const void* p) {
    uint32_t a;
    asm("{ .reg .u64 t; cvta.to.shared.u64 t, %1; cvt.u32.u64 %0, t; }" : "=r"(a) : "l"(p));
    return a;
}

#define CP_ASYNC16(dst, src) \
    asm volatile("cp.async.cg.shared.global [%0], [%1], 16;" :: "r"(dst), "l"(src))
#define CP_COMMIT()  asm volatile("cp.async.commit_group;" ::: "memory")
#define CP_WAIT1()   asm volatile("cp.async.wait_group 1;" ::: "memory")
#define CP_WAIT0()   asm volatile("cp.async.wait_group 0;" ::: "memory")

static __device__ __forceinline__ uint32_t lds_u32(uint32_t addr) {
    uint32_t v;
    asm volatile("ld.shared.b32 %0, [%1];" : "=r"(v) : "r"(addr));
    return v;
}
static __device__ __forceinline__ float lds_f32(uint32_t addr) {
    float v;
    asm volatile("ld.shared.f32 %0, [%1];" : "=f"(v) : "r"(addr));
    return v;
}
// tf32 destination must be a .b32 register ("=r"), NOT .f32
static __device__ __forceinline__ uint32_t f2tf32(float f) {
    uint32_t u;
    asm("cvt.rna.tf32.f32 %0, %1;" : "=r"(u) : "f"(f));
    return u;
}
static __device__ __forceinline__ void mma_tf32(float* c, uint32_t a0, uint32_t a1,
                                                uint32_t a2, uint32_t a3,
                                                uint32_t b0, uint32_t b1) {
    asm volatile(
        "mma.sync.aligned.m16n8k8.row.col.f32.tf32.tf32.f32 "
        "{%0,%1,%2,%3}, {%4,%5,%6,%7}, {%8,%9}, {%0,%1,%2,%3};"
        : "+f"(c[0]), "+f"(c[1]), "+f"(c[2]), "+f"(c[3])
        : "r"(a0), "r"(a1), "r"(a2), "r"(a3), "r"(b0), "r"(b1));
}

// ---------------------------------------------------------------------------
// Kernel 1: precompute A' (tf32-rounded). Exact integer angle reduction:
// j = ((2n+1)*k) mod 4N ; ang = pi * j / (2N*2)
// ---------------------------------------------------------------------------
__global__ void __launch_bounds__(256) precompute_A(const float* __restrict__ D,
                                                    const int* __restrict__ P) {
    int idx = blockIdx.x * 256 + threadIdx.x;
    int d = idx >> 13;            // / 8192
    int k = idx & (ND - 1);
    int n = P[d];
    unsigned j = ((unsigned)(2 * n + 1) * (unsigned)k) & (4u * ND - 1u);   // mod 32768
    float ang = (float)j * 1.9174759848570515e-4f;                         // pi/16384
    float c = cosf(ang);
    float w = (k == 0) ? (0.5f / (float)ND) : (1.0f / (float)ND);
    float v = D[k] * w * c;
    g_A[idx] = __uint_as_float(f2tf32(v));    // store tf32-rounded bits
}

// ---------------------------------------------------------------------------
// Kernel 2: out[1024,4096] = A'[1024,8192] @ M[8192,4096] with mma.sync tf32.
// CTA tile 128(d) x 128(m), KC=32, 3-stage cp.async pipeline, 4 warps (2x2),
// warp tile 64x64 (4 m-frags x 8 n-frags of m16n8k8).
// SMEM (padded rows, no transposes, bank-conflict-free):
//   As[m 0..127][k 0..31]  row stride 144 B  (36 words  = 4 mod 32)
//   Bs[k 0..31][m 0..127]  row stride 544 B  (136 words = 8 mod 32)
// ---------------------------------------------------------------------------
#define A_STRIDE 144u
#define B_STRIDE 544u
#define A_BYTES  (128u * A_STRIDE)               /* 18432 */
#define B_BYTES  (32u * B_STRIDE)                /* 17408 */
#define BUF_BYTES (A_BYTES + B_BYTES)            /* 35840 */
#define NSTAGE   3u
#define SMEM_REQ (NSTAGE * BUF_BYTES + 16u)      /* 107536 */

__global__ void __launch_bounds__(128, 2) srft_gemm(const float* __restrict__ Mmat,
                                                    float* __restrict__ out) {
    extern __shared__ char smem[];
    const uint32_t sb = smem_u32(smem);

    const int tid = threadIdx.x;
    const int wid = tid >> 5;
    const int lid = tid & 31;
    const int dt0 = blockIdx.x * 128;        // d-tile (8)
    const int nt0 = blockIdx.y * 128;        // m-tile (32)
    const int mw  = (wid >> 1) * 64;         // warp 64 rows
    const int nw  = (wid & 1) * 64;          // warp 64 cols

    const float* Aptr = g_A + (size_t)dt0 * ND;
    const float* Bptr = Mmat + nt0;

    float acc[4][8][4];
    #pragma unroll
    for (int i = 0; i < 4; i++)
        #pragma unroll
        for (int j = 0; j < 8; j++)
            #pragma unroll
            for (int q = 0; q < 4; q++) acc[i][j][q] = 0.f;

    // A fill: 1024 quads / 128 thr = 8 iters:  r = idx>>3 (row m), q = idx&7
    // B fill: 1024 quads / 128 thr = 8 iters:  k = idx>>5,          q = idx&31
    auto fill = [&](uint32_t buf, int k0) {
        const uint32_t ab = sb + buf * BUF_BYTES;
        const uint32_t bb = ab + A_BYTES;
        #pragma unroll
        for (int i = 0; i < 8; i++) {
            int idx = tid + i * 128;
            int r = idx >> 3, q = idx & 7;
            CP_ASYNC16(ab + (uint32_t)r * A_STRIDE + (uint32_t)q * 16u,
                       Aptr + (size_t)r * ND + k0 + q * 4);
        }
        #pragma unroll
        for (int i = 0; i < 8; i++) {
            int idx = tid + i * 128;
            int k = idx >> 5, q = idx & 31;
            CP_ASYNC16(bb + (uint32_t)k * B_STRIDE + (uint32_t)q * 16u,
                       Bptr + (size_t)(k0 + k) * MCOLS + q * 4);
        }
        CP_COMMIT();
    };

    fill(0, 0);
    fill(1, KC);

    for (int c = 0; c < NCHUNK; c++) {
        const uint32_t buf = (uint32_t)(c % 3);
        CP_WAIT1();              // chunk c's fill complete (<=1 group pending)
        __syncthreads();         // all warps past compute of c-1; fills visible

        if (c + 2 < NCHUNK) fill((uint32_t)((c + 2) % 3), (c + 2) * KC);

        const uint32_t ab = sb + buf * BUF_BYTES;
        const uint32_t bb = ab + A_BYTES;
        const uint32_t a_base = ab + (uint32_t)(mw + (lid >> 2)) * A_STRIDE + (uint32_t)(lid & 3) * 4u;
        const uint32_t b_base = bb + (uint32_t)(lid & 3) * B_STRIDE + (uint32_t)(nw + (lid >> 2)) * 4u;

        #pragma unroll
        for (int kk = 0; kk < 4; kk++) {
            // B fragments: B[k][n], k = kk*8 + lane%4 (+4), n = nw + nf*8 + lane/4
            uint32_t bfr[8][2];
            #pragma unroll
            for (int nf = 0; nf < 8; nf++) {
                uint32_t a0 = b_base + (uint32_t)(kk * 8) * B_STRIDE + (uint32_t)(nf * 8) * 4u;
                bfr[nf][0] = f2tf32(lds_f32(a0));
                bfr[nf][1] = f2tf32(lds_f32(a0 + 4u * B_STRIDE));
            }
            #pragma unroll
            for (int ms = 0; ms < 4; ms++) {
                uint32_t aa = a_base + (uint32_t)(ms * 16) * A_STRIDE + (uint32_t)(kk * 8) * 4u;
                uint32_t a0 = lds_u32(aa);
                uint32_t a1 = lds_u32(aa + 8u * A_STRIDE);
                uint32_t a2 = lds_u32(aa + 16u);
                uint32_t a3 = lds_u32(aa + 8u * A_STRIDE + 16u);
                #pragma unroll
                for (int nf = 0; nf < 8; nf++)
                    mma_tf32(acc[ms][nf], a0, a1, a2, a3, bfr[nf][0], bfr[nf][1]);
            }
        }
    }

    // Epilogue: direct STG (16 MB total, negligible)
    const int r_base = dt0 + mw + (lid >> 2);
    const int c_base = nt0 + nw + (lid & 3) * 2;
    #pragma unroll
    for (int ms = 0; ms < 4; ms++) {
        #pragma unroll
        for (int nf = 0; nf < 8; nf++) {
            int r0 = r_base + ms * 16;
            int cc = c_base + nf * 8;
            float2 v0 = make_float2(acc[ms][nf][0], acc[ms][nf][1]);
            float2 v1 = make_float2(acc[ms][nf][2], acc[ms][nf][3]);
            *reinterpret_cast<float2*>(out + (size_t)r0 * MCOLS + cc) = v0;
            *reinterpret_cast<float2*>(out + (size_t)(r0 + 8) * MCOLS + cc) = v1;
        }
    }
}

// ---------------------------------------------------------------------------
extern "C" void kernel_launch(void* const* d_in, const int* in_sizes, int n_in,
                              void* d_out, int out_size) {
    const float* Mmat = nullptr;
    const float* D = nullptr;
    const int*   P = nullptr;
    for (int i = 0; i < n_in; i++) {
        if (in_sizes[i] == ND * MCOLS)      Mmat = (const float*)d_in[i];
        else if (in_sizes[i] == ND)         D    = (const float*)d_in[i];
        else if (in_sizes[i] == DSK)        P    = (const int*)d_in[i];
    }

    precompute_A<<<(DSK * ND) / 256, 256>>>(D, P);

    cudaFuncSetAttribute(srft_gemm, cudaFuncAttributeMaxDynamicSharedMemorySize, SMEM_REQ);
    dim3 grid(8, 32);
    srft_gemm<<<grid, 128, SMEM_REQ>>>(Mmat, (float*)d_out);
}

// round 9
// speedup vs baseline: 1.1308x; 1.0051x over previous
#include <cuda_runtime.h>
#include <cstdint>
#include <cstddef>

#define ND     8192
#define DSK    1024
#define MCOLS  4096
#define KC     32
#define NCHUNK (ND / KC)          /* 256 */

// A' scratch: A'[d][k] = D[k]*w(k)*cos(pi*(2*P[d]+1)*k/(2N)), tf32-rounded bits
__device__ float g_A[(size_t)DSK * ND];

// ---------------------------------------------------------------------------
static __device__ __forceinline__ uint32_t smem_u32(const void* p) {
    uint32_t a;
    asm("{ .reg .u64 t; cvta.to.shared.u64 t, %1; cvt.u32.u64 %0, t; }" : "=r"(a) : "l"(p));
    return a;
}

#define CP_ASYNC16(dst, src) \
    asm volatile("cp.async.cg.shared.global [%0], [%1], 16;" :: "r"(dst), "l"(src))
#define CP_COMMIT()  asm volatile("cp.async.commit_group;" ::: "memory")
#define CP_WAIT1()   asm volatile("cp.async.wait_group 1;" ::: "memory")

static __device__ __forceinline__ float lds_f32(uint32_t addr) {
    float v;
    asm volatile("ld.shared.f32 %0, [%1];" : "=f"(v) : "r"(addr));
    return v;
}
// tf32 destination must be a .b32 register ("=r"), NOT .f32
static __device__ __forceinline__ uint32_t f2tf32(float f) {
    uint32_t u;
    asm("cvt.rna.tf32.f32 %0, %1;" : "=r"(u) : "f"(f));
    return u;
}
// ldmatrix x4: tf32 16x8 A fragment == x4 b16 LDSM over the same tile.
// Lane l supplies the row address: row = l&15, 16B-quad = l>>4.
#define LDSM4(r, addr) \
    asm volatile("ldmatrix.sync.aligned.m8n8.x4.shared.b16 {%0,%1,%2,%3}, [%4];" \
        : "=r"((r)[0]), "=r"((r)[1]), "=r"((r)[2]), "=r"((r)[3]) : "r"(addr))

static __device__ __forceinline__ void mma_tf32(float* c, uint32_t a0, uint32_t a1,
                                                uint32_t a2, uint32_t a3,
                                                uint32_t b0, uint32_t b1) {
    asm volatile(
        "mma.sync.aligned.m16n8k8.row.col.f32.tf32.tf32.f32 "
        "{%0,%1,%2,%3}, {%4,%5,%6,%7}, {%8,%9}, {%0,%1,%2,%3};"
        : "+f"(c[0]), "+f"(c[1]), "+f"(c[2]), "+f"(c[3])
        : "r"(a0), "r"(a1), "r"(a2), "r"(a3), "r"(b0), "r"(b1));
}

// ---------------------------------------------------------------------------
// Kernel 1: precompute A' (tf32-rounded). Exact integer angle reduction:
// j = ((2n+1)*k) mod 4N ; ang = pi * j / (2N*2)
// ---------------------------------------------------------------------------
__global__ void __launch_bounds__(256) precompute_A(const float* __restrict__ D,
                                                    const int* __restrict__ P) {
    int idx = blockIdx.x * 256 + threadIdx.x;
    int d = idx >> 13;            // / 8192
    int k = idx & (ND - 1);
    int n = P[d];
    unsigned j = ((unsigned)(2 * n + 1) * (unsigned)k) & (4u * ND - 1u);   // mod 32768
    float ang = (float)j * 1.9174759848570515e-4f;                         // pi/16384
    float c = cosf(ang);
    float w = (k == 0) ? (0.5f / (float)ND) : (1.0f / (float)ND);
    float v = D[k] * w * c;
    g_A[idx] = __uint_as_float(f2tf32(v));    // store tf32-rounded bits
}

// ---------------------------------------------------------------------------
// Kernel 2: out[1024,4096] = A'[1024,8192] @ M[8192,4096] with mma.sync tf32.
// CTA tile 128(d) x 128(m), KC=32, 3-stage cp.async pipeline, 4 warps (2x2),
// warp tile 64x64. A frags via ldmatrix.x4; A/B frags double-buffered in regs
// across the 4 kk steps so LDS/LDSM latency overlaps the 32 MMAs of kk.
// SMEM (padded rows, no transposes, bank/LDSM-conflict-free):
//   As[m 0..127][k 0..31]  row stride 144 B  (36 words  = 4 mod 32)
//   Bs[k 0..31][m 0..127]  row stride 544 B  (136 words = 8 mod 32)
// ---------------------------------------------------------------------------
#define A_STRIDE 144u
#define B_STRIDE 544u
#define A_BYTES  (128u * A_STRIDE)               /* 18432 */
#define B_BYTES  (32u * B_STRIDE)                /* 17408 */
#define BUF_BYTES (A_BYTES + B_BYTES)            /* 35840 */
#define NSTAGE   3u
#define SMEM_REQ (NSTAGE * BUF_BYTES + 16u)      /* 107536 */

__global__ void __launch_bounds__(128, 2) srft_gemm(const float* __restrict__ Mmat,
                                                    float* __restrict__ out) {
    extern __shared__ char smem[];
    const uint32_t sb = smem_u32(smem);

    const int tid = threadIdx.x;
    const int wid = tid >> 5;
    const int lid = tid & 31;
    const int dt0 = blockIdx.x * 128;        // d-tile (8)
    const int nt0 = blockIdx.y * 128;        // m-tile (32)
    const int mw  = (wid >> 1) * 64;         // warp 64 rows
    const int nw  = (wid & 1) * 64;          // warp 64 cols

    const float* Aptr = g_A + (size_t)dt0 * ND;
    const float* Bptr = Mmat + nt0;

    float acc[4][8][4];
    #pragma unroll
    for (int i = 0; i < 4; i++)
        #pragma unroll
        for (int j = 0; j < 8; j++)
            #pragma unroll
            for (int q = 0; q < 4; q++) acc[i][j][q] = 0.f;

    // A fill: 1024 quads / 128 thr = 8 iters:  r = idx>>3 (row m), q = idx&7
    // B fill: 1024 quads / 128 thr = 8 iters:  k = idx>>5,          q = idx&31
    auto fill = [&](uint32_t buf, int k0) {
        const uint32_t ab = sb + buf * BUF_BYTES;
        const uint32_t bb = ab + A_BYTES;
        #pragma unroll
        for (int i = 0; i < 8; i++) {
            int idx = tid + i * 128;
            int r = idx >> 3, q = idx & 7;
            CP_ASYNC16(ab + (uint32_t)r * A_STRIDE + (uint32_t)q * 16u,
                       Aptr + (size_t)r * ND + k0 + q * 4);
        }
        #pragma unroll
        for (int i = 0; i < 8; i++) {
            int idx = tid + i * 128;
            int k = idx >> 5, q = idx & 31;
            CP_ASYNC16(bb + (uint32_t)k * B_STRIDE + (uint32_t)q * 16u,
                       Bptr + (size_t)(k0 + k) * MCOLS + q * 4);
        }
        CP_COMMIT();
    };

    fill(0, 0);
    fill(1, KC);

    for (int c = 0; c < NCHUNK; c++) {
        const uint32_t buf = (uint32_t)(c % 3);
        CP_WAIT1();              // chunk c's fill complete (<=1 group pending)
        __syncthreads();         // all warps past compute of c-1; fills visible

        if (c + 2 < NCHUNK) fill((uint32_t)((c + 2) % 3), (c + 2) * KC);

        const uint32_t ab = sb + buf * BUF_BYTES;
        const uint32_t bb = ab + A_BYTES;
        // LDSM base: lane l -> row (l&15) of warp tile, quad (l>>4)
        const uint32_t a_ldsm = ab + (uint32_t)(mw + (lid & 15)) * A_STRIDE
                                   + (uint32_t)((lid >> 4) * 16);
        const uint32_t b_base = bb + (uint32_t)(lid & 3) * B_STRIDE
                                   + (uint32_t)(nw + (lid >> 2)) * 4u;

        uint32_t afr[2][4][4];
        uint32_t bfr[2][8][2];

        // Preload kk = 0
        #pragma unroll
        for (int nf = 0; nf < 8; nf++) {
            uint32_t a0 = b_base + (uint32_t)(nf * 8) * 4u;
            bfr[0][nf][0] = f2tf32(lds_f32(a0));
            bfr[0][nf][1] = f2tf32(lds_f32(a0 + 4u * B_STRIDE));
        }
        #pragma unroll
        for (int ms = 0; ms < 4; ms++)
            LDSM4(afr[0][ms], a_ldsm + (uint32_t)(ms * 16) * A_STRIDE);

        #pragma unroll
        for (int kk = 0; kk < 4; kk++) {
            const int cur = kk & 1, nxt = cur ^ 1;
            if (kk < 3) {
                // Prefetch kk+1 fragments (independent of the MMAs below)
                #pragma unroll
                for (int nf = 0; nf < 8; nf++) {
                    uint32_t a0 = b_base + (uint32_t)((kk + 1) * 8) * B_STRIDE
                                         + (uint32_t)(nf * 8) * 4u;
                    bfr[nxt][nf][0] = f2tf32(lds_f32(a0));
                    bfr[nxt][nf][1] = f2tf32(lds_f32(a0 + 4u * B_STRIDE));
                }
                #pragma unroll
                for (int ms = 0; ms < 4; ms++)
                    LDSM4(afr[nxt][ms], a_ldsm + (uint32_t)(ms * 16) * A_STRIDE
                                               + (uint32_t)((kk + 1) * 32));
            }
            #pragma unroll
            for (int ms = 0; ms < 4; ms++)
                #pragma unroll
                for (int nf = 0; nf < 8; nf++)
                    mma_tf32(acc[ms][nf],
                             afr[cur][ms][0], afr[cur][ms][1],
                             afr[cur][ms][2], afr[cur][ms][3],
                             bfr[cur][nf][0], bfr[cur][nf][1]);
        }
    }

    // Epilogue: direct STG (16 MB total, negligible)
    const int r_base = dt0 + mw + (lid >> 2);
    const int c_base = nt0 + nw + (lid & 3) * 2;
    #pragma unroll
    for (int ms = 0; ms < 4; ms++) {
        #pragma unroll
        for (int nf = 0; nf < 8; nf++) {
            int r0 = r_base + ms * 16;
            int cc = c_base + nf * 8;
            float2 v0 = make_float2(acc[ms][nf][0], acc[ms][nf][1]);
            float2 v1 = make_float2(acc[ms][nf][2], acc[ms][nf][3]);
            *reinterpret_cast<float2*>(out + (size_t)r0 * MCOLS + cc) = v0;
            *reinterpret_cast<float2*>(out + (size_t)(r0 + 8) * MCOLS + cc) = v1;
        }
    }
}

// ---------------------------------------------------------------------------
extern "C" void kernel_launch(void* const* d_in, const int* in_sizes, int n_in,
                              void* d_out, int out_size) {
    const float* Mmat = nullptr;
    const float* D = nullptr;
    const int*   P = nullptr;
    for (int i = 0; i < n_in; i++) {
        if (in_sizes[i] == ND * MCOLS)      Mmat = (const float*)d_in[i];
        else if (in_sizes[i] == ND)         D    = (const float*)d_in[i];
        else if (in_sizes[i] == DSK)        P    = (const int*)d_in[i];
    }

    precompute_A<<<(DSK * ND) / 256, 256>>>(D, P);

    cudaFuncSetAttribute(srft_gemm, cudaFuncAttributeMaxDynamicSharedMemorySize, SMEM_REQ);
    dim3 grid(8, 32);
    srft_gemm<<<grid, 128, SMEM_REQ>>>(Mmat, (float*)d_out);
}